// round 2
// baseline (speedup 1.0000x reference)
#include <cuda_runtime.h>
#include <math.h>

// Problem constants
#define N_Q   65536      // B*H*W query vectors
#define N_E   1024       // codebook entries
#define DIM   64         // embedding dim (== C)
#define HW    4096       // H*W
#define NB    16         // batch
#define TOTAL 4194304    // NB*DIM*HW = 16*64*4096 elements of inputs/quantized

// Output layout (tuple flattened in return order):
// loss[1] | quantized[TOTAL] | perplexity[1] | encodings[N_Q*N_E]
#define O_LOSS  0
#define O_QUANT 1UL
#define O_PERP  4194305UL
#define O_ENC   4194306UL

// GEMM tiling
#define TQ 128           // queries per block
#define TE 128           // codes per chunk
#define LDP 132          // padded leading dim in shared (floats)

// ---------------- scratch (device globals; no allocation allowed) -------------
__device__ int   g_idx[N_Q];
__device__ int   g_counts[N_E];
__device__ float g_loss_accum;
__device__ float g_enorm_half[N_E];

// ---------------- kernel Z: zero accumulators --------------------------------
__global__ void zero_kernel() {
    int t = threadIdx.x;
    if (t < N_E) g_counts[t] = 0;
    if (t == 0)  g_loss_accum = 0.0f;
}

// ---------------- kernel N: 0.5 * ||e_j||^2 ----------------------------------
__global__ void enorm_kernel(const float* __restrict__ ew) {
    int j = blockIdx.x * blockDim.x + threadIdx.x;
    if (j < N_E) {
        const float4* p = (const float4*)(ew + (size_t)j * DIM);
        float s = 0.0f;
#pragma unroll
        for (int i = 0; i < DIM / 4; i++) {
            float4 v = p[i];
            s += v.x * v.x + v.y * v.y + v.z * v.z + v.w * v.w;
        }
        g_enorm_half[j] = 0.5f * s;
    }
}

// ---------------- kernel A: fused GEMM + argmin -------------------------------
// dist_j (up to +||x||^2 const) = 0.5*||e_j||^2 - x . e_j ; argmin over j.
// Block: 256 threads = 16x16, each thread 8 queries x 8 codes.
extern __shared__ float smem[];
__global__ __launch_bounds__(256, 2) void argmin_kernel(const float* __restrict__ x,
                                                        const float* __restrict__ ew) {
    float* Xs = smem;                  // [DIM][LDP] : Xs[k*LDP + q]
    float* Es = smem + DIM * LDP;      // [DIM][LDP] : Es[k*LDP + j]

    int tid = threadIdx.x;
    int tx = tid & 15;       // code sub-tile
    int ty = tid >> 4;       // query sub-tile
    int qbase = blockIdx.x * TQ;

    // inputs are NCHW: element (b, k, hw) at  b*DIM*HW + k*HW + hw ; query n = b*HW + hw.
    // A 128-query tile never crosses a batch boundary (HW % TQ == 0).
    const float* xb = x + ((size_t)(qbase >> 12) * (DIM * HW)) + (qbase & (HW - 1));

    // Load X tile (coalesced per k-row)
    for (int i = tid; i < DIM * TQ; i += 256) {
        int k = i >> 7;            // /128
        int q = i & (TQ - 1);
        Xs[k * LDP + q] = xb[(size_t)k * HW + q];
    }

    float bestVal[8];
    int   bestIdx[8];
#pragma unroll
    for (int i = 0; i < 8; i++) { bestVal[i] = 3.4e38f; bestIdx[i] = 0; }

    for (int chunk = 0; chunk < N_E / TE; chunk++) {
        int j0 = chunk * TE;
        __syncthreads();   // X stores visible / previous Es consumers done
        // Load E chunk transposed: Es[k][j]  (global reads coalesced along k)
        for (int i = tid; i < TE * DIM; i += 256) {
            int j = i >> 6;            // /64
            int k = i & (DIM - 1);
            Es[k * LDP + j] = ew[(size_t)(j0 + j) * DIM + k];
        }
        __syncthreads();

        float acc[8][8];
#pragma unroll
        for (int i = 0; i < 8; i++)
#pragma unroll
            for (int j = 0; j < 8; j++) acc[i][j] = 0.0f;

#pragma unroll 4
        for (int k = 0; k < DIM; k++) {
            float4 xa = *(const float4*)&Xs[k * LDP + ty * 8];
            float4 xc = *(const float4*)&Xs[k * LDP + ty * 8 + 4];
            float4 ea = *(const float4*)&Es[k * LDP + tx * 8];
            float4 eb = *(const float4*)&Es[k * LDP + tx * 8 + 4];
            float xv[8] = {xa.x, xa.y, xa.z, xa.w, xc.x, xc.y, xc.z, xc.w};
            float ev[8] = {ea.x, ea.y, ea.z, ea.w, eb.x, eb.y, eb.z, eb.w};
#pragma unroll
            for (int i = 0; i < 8; i++)
#pragma unroll
                for (int j = 0; j < 8; j++)
                    acc[i][j] = fmaf(xv[i], ev[j], acc[i][j]);
        }

        // Epilogue: local argmin then 16-lane reduction along the code dim
        float en[8];
#pragma unroll
        for (int j = 0; j < 8; j++) en[j] = g_enorm_half[j0 + tx * 8 + j];

#pragma unroll
        for (int i = 0; i < 8; i++) {
            float v = en[0] - acc[i][0];
            int jj = 0;
#pragma unroll
            for (int j = 1; j < 8; j++) {
                float c = en[j] - acc[i][j];
                if (c < v) { v = c; jj = j; }
            }
            int gj = j0 + tx * 8 + jj;
#pragma unroll
            for (int m = 1; m < 16; m <<= 1) {
                float ov = __shfl_xor_sync(0xffffffffu, v, m);
                int   og = __shfl_xor_sync(0xffffffffu, gj, m);
                if (ov < v || (ov == v && og < gj)) { v = ov; gj = og; }
            }
            if (v < bestVal[i]) { bestVal[i] = v; bestIdx[i] = gj; }
        }
    }

    if (tx == 0) {
#pragma unroll
        for (int i = 0; i < 8; i++) {
            g_idx[qbase + ty * 8 + i] = bestIdx[i];
            atomicAdd(&g_counts[bestIdx[i]], 1);
        }
    }
}

// ---------------- kernel B: gather + straight-through + loss partial ----------
__global__ void quant_loss_kernel(const float* __restrict__ x,
                                  const float* __restrict__ ew,
                                  float* __restrict__ out) {
    int t = blockIdx.x * 256 + threadIdx.x;   // over TOTAL elements, NCHW order
    int hw = t & (HW - 1);
    int c  = (t >> 12) & (DIM - 1);
    int b  = t >> 18;
    int n  = b * HW + hw;
    int idx = g_idx[n];
    float q  = ew[(size_t)idx * DIM + c];
    float xv = x[t];
    float d  = q - xv;
    out[O_QUANT + t] = xv + d;   // straight-through forward value (== q)
    float s = d * d;
#pragma unroll
    for (int m = 16; m > 0; m >>= 1) s += __shfl_xor_sync(0xffffffffu, s, m);
    __shared__ float ws[8];
    int lane = threadIdx.x & 31, w = threadIdx.x >> 5;
    if (lane == 0) ws[w] = s;
    __syncthreads();
    if (w == 0) {
        float v = (lane < 8) ? ws[lane] : 0.0f;
#pragma unroll
        for (int m = 4; m > 0; m >>= 1) v += __shfl_xor_sync(0xffffffffu, v, m);
        if (lane == 0) atomicAdd(&g_loss_accum, v);
    }
}

// ---------------- kernel C: one-hot encodings (zeros + the 1, single pass) ----
// enc region starts at float offset O_ENC (8B-aligned) -> float2 stores.
__global__ void enc_kernel(float* __restrict__ out) {
    int n = blockIdx.x;
    int idx = g_idx[n];
    float2* row = (float2*)(out + O_ENC + (size_t)n * N_E);
    int t = threadIdx.x;   // 256 threads, 512 float2 slots per row
#pragma unroll
    for (int r = 0; r < 2; r++) {
        int slot = t + r * 256;
        float2 v = make_float2(0.0f, 0.0f);
        if (slot == (idx >> 1)) {
            if (idx & 1) v.y = 1.0f; else v.x = 1.0f;
        }
        row[slot] = v;
    }
}

// ---------------- kernel D: perplexity + loss finalize ------------------------
__global__ void final_kernel(float* __restrict__ out) {
    int t = threadIdx.x;   // 1024 threads
    float p = (float)g_counts[t] * (1.0f / 65536.0f);
    float s = p * logf(p + 1e-10f);
#pragma unroll
    for (int m = 16; m > 0; m >>= 1) s += __shfl_xor_sync(0xffffffffu, s, m);
    __shared__ float ws[32];
    int lane = t & 31, w = t >> 5;
    if (lane == 0) ws[w] = s;
    __syncthreads();
    if (w == 0) {
        float v = ws[lane];
#pragma unroll
        for (int m = 16; m > 0; m >>= 1) v += __shfl_xor_sync(0xffffffffu, v, m);
        if (lane == 0) {
            out[O_PERP] = expf(-v);
            out[O_LOSS] = 1.25f * g_loss_accum * (1.0f / (float)TOTAL);
        }
    }
}

// ---------------- launch ------------------------------------------------------
extern "C" void kernel_launch(void* const* d_in, const int* in_sizes, int n_in,
                              void* d_out, int out_size) {
    // Defensive: identify inputs by size (inputs = 4,194,304 ; embed = 65,536)
    const float* x  = (const float*)d_in[0];
    const float* ew = (const float*)d_in[1];
    if (n_in >= 2 && in_sizes[0] == N_E * DIM && in_sizes[1] == TOTAL) {
        x  = (const float*)d_in[1];
        ew = (const float*)d_in[0];
    }
    float* out = (float*)d_out;

    zero_kernel<<<1, 1024>>>();
    enorm_kernel<<<N_E / 128, 128>>>(ew);

    size_t smem = (size_t)2 * DIM * LDP * sizeof(float);   // 67,584 B
    cudaFuncSetAttribute(argmin_kernel,
                         cudaFuncAttributeMaxDynamicSharedMemorySize, (int)smem);
    argmin_kernel<<<N_Q / TQ, 256, smem>>>(x, ew);

    quant_loss_kernel<<<TOTAL / 256, 256>>>(x, ew, out);
    enc_kernel<<<N_Q, 256>>>(out);
    final_kernel<<<1, 1024>>>(out);
}

// round 3
// speedup vs baseline: 1.0530x; 1.0530x over previous
#include <cuda_runtime.h>
#include <math.h>

// Problem constants
#define N_Q   65536      // B*H*W query vectors
#define N_E   1024       // codebook entries
#define DIM   64         // embedding dim (== C)
#define HW    4096       // H*W
#define NB    16         // batch
#define TOTAL 4194304    // NB*DIM*HW elements of inputs/quantized

// Output layout: loss[1] | quantized[TOTAL] | perplexity[1] | encodings[N_Q*N_E]
#define O_LOSS  0
#define O_QUANT 1UL
#define O_PERP  4194305UL
#define O_ENC   4194306UL

// GEMM tiling
#define TQ 128
#define TE 128
#define LDP 132          // padded leading dim in shared (floats); 528B rows keep 16B align

// ---------------- scratch ------------------------------------------------------
__device__ int   g_idx[N_Q];
__device__ int   g_counts[N_E];
__device__ float g_loss_accum;
__device__ float g_enorm_half[N_E];

// ---------------- packed f32x2 helpers ------------------------------------------
__device__ __forceinline__ void ffma2(unsigned long long& acc,
                                      unsigned long long a, unsigned long long b) {
    asm("fma.rn.f32x2 %0, %1, %2, %0;" : "+l"(acc) : "l"(a), "l"(b));
}
__device__ __forceinline__ unsigned long long pack2(float x) {
    unsigned long long r;
    asm("mov.b64 %0, {%1, %1};" : "=l"(r) : "f"(x));
    return r;
}
__device__ __forceinline__ void unpack2(unsigned long long v, float& lo, float& hi) {
    asm("mov.b64 {%0, %1}, %2;" : "=f"(lo), "=f"(hi) : "l"(v));
}

// ---------------- kernel ZN: zero accumulators + 0.5*||e||^2 -------------------
__global__ void init_kernel(const float* __restrict__ ew) {
    int j = blockIdx.x * blockDim.x + threadIdx.x;   // 1024 threads total
    g_counts[j] = 0;
    if (j == 0) g_loss_accum = 0.0f;
    const float4* p = (const float4*)(ew + (size_t)j * DIM);
    float s = 0.0f;
#pragma unroll
    for (int i = 0; i < DIM / 4; i++) {
        float4 v = p[i];
        s += v.x * v.x + v.y * v.y + v.z * v.z + v.w * v.w;
    }
    g_enorm_half[j] = 0.5f * s;
}

// ---------------- kernel A: fused GEMM + argmin (packed f32x2) -----------------
// dist_j (up to +||x||^2) = 0.5*||e_j||^2 - x.e_j ; exact fp32 arithmetic.
extern __shared__ float smem[];
__global__ __launch_bounds__(256, 2) void argmin_kernel(const float* __restrict__ x,
                                                        const float* __restrict__ ew) {
    float* Xs = smem;                  // [DIM][LDP] : Xs[k*LDP + q]
    float* Es = smem + DIM * LDP;      // [DIM][LDP] : Es[k*LDP + j]

    int tid = threadIdx.x;
    int tx = tid & 15;       // code sub-tile (8 codes = 4 pairs)
    int ty = tid >> 4;       // query sub-tile (8 queries)
    int qbase = blockIdx.x * TQ;

    // NCHW: element (b,k,hw) at b*DIM*HW + k*HW + hw ; query n = b*HW + hw.
    const float* xb = x + ((size_t)(qbase >> 12) * (DIM * HW)) + (qbase & (HW - 1));

    for (int i = tid; i < DIM * TQ; i += 256) {
        int k = i >> 7;
        int q = i & (TQ - 1);
        Xs[k * LDP + q] = xb[(size_t)k * HW + q];
    }

    float bestVal[8];
    int   bestIdx[8];
#pragma unroll
    for (int i = 0; i < 8; i++) { bestVal[i] = 3.4e38f; bestIdx[i] = 0; }

    for (int chunk = 0; chunk < N_E / TE; chunk++) {
        int j0 = chunk * TE;
        __syncthreads();
        for (int i = tid; i < TE * DIM; i += 256) {
            int j = i >> 6;
            int k = i & (DIM - 1);
            Es[k * LDP + j] = ew[(size_t)(j0 + j) * DIM + k];
        }
        __syncthreads();

        unsigned long long acc2[8][4];
#pragma unroll
        for (int i = 0; i < 8; i++)
#pragma unroll
            for (int jp = 0; jp < 4; jp++) acc2[i][jp] = 0ULL;

#pragma unroll 4
        for (int k = 0; k < DIM; k++) {
            float4 xa = *(const float4*)&Xs[k * LDP + ty * 8];
            float4 xc = *(const float4*)&Xs[k * LDP + ty * 8 + 4];
            ulonglong2 ea = *(const ulonglong2*)&Es[k * LDP + tx * 8];
            ulonglong2 eb = *(const ulonglong2*)&Es[k * LDP + tx * 8 + 4];
            unsigned long long ev[4] = {ea.x, ea.y, eb.x, eb.y};
            float xv[8] = {xa.x, xa.y, xa.z, xa.w, xc.x, xc.y, xc.z, xc.w};
#pragma unroll
            for (int i = 0; i < 8; i++) {
                unsigned long long xx = pack2(xv[i]);
#pragma unroll
                for (int jp = 0; jp < 4; jp++)
                    ffma2(acc2[i][jp], xx, ev[jp]);
            }
        }

        float en[8];
#pragma unroll
        for (int j = 0; j < 8; j++) en[j] = g_enorm_half[j0 + tx * 8 + j];

#pragma unroll
        for (int i = 0; i < 8; i++) {
            float a[8];
#pragma unroll
            for (int jp = 0; jp < 4; jp++) unpack2(acc2[i][jp], a[2 * jp], a[2 * jp + 1]);
            float v = en[0] - a[0];
            int jj = 0;
#pragma unroll
            for (int j = 1; j < 8; j++) {
                float c = en[j] - a[j];
                if (c < v) { v = c; jj = j; }
            }
            int gj = j0 + tx * 8 + jj;
#pragma unroll
            for (int m = 1; m < 16; m <<= 1) {
                float ov = __shfl_xor_sync(0xffffffffu, v, m);
                int   og = __shfl_xor_sync(0xffffffffu, gj, m);
                if (ov < v || (ov == v && og < gj)) { v = ov; gj = og; }
            }
            if (v < bestVal[i]) { bestVal[i] = v; bestIdx[i] = gj; }
        }
    }

    if (tx == 0) {
#pragma unroll
        for (int i = 0; i < 8; i++) {
            g_idx[qbase + ty * 8 + i] = bestIdx[i];
            atomicAdd(&g_counts[bestIdx[i]], 1);
        }
    }
}

// ---------------- kernel B: gather + straight-through + loss (x4 vectorized) ---
__global__ void quant_loss_kernel(const float* __restrict__ x,
                                  const float* __restrict__ ew,
                                  float* __restrict__ out) {
    int t4 = blockIdx.x * 256 + threadIdx.x;   // TOTAL/4 threads
    int e0 = t4 * 4;                           // 4 consecutive hw, same (b,c)
    int hw = e0 & (HW - 1);
    int c  = (e0 >> 12) & (DIM - 1);
    int b  = e0 >> 18;
    int n  = b * HW + hw;
    int4   idx4 = *(const int4*)&g_idx[n];
    float4 xv   = *(const float4*)&x[e0];
    float4 q;
    q.x = ew[(size_t)idx4.x * DIM + c];
    q.y = ew[(size_t)idx4.y * DIM + c];
    q.z = ew[(size_t)idx4.z * DIM + c];
    q.w = ew[(size_t)idx4.w * DIM + c];
    float4 d = make_float4(q.x - xv.x, q.y - xv.y, q.z - xv.z, q.w - xv.w);
    // quantized region is only 4B-aligned (offset 1) -> scalar stores
    out[O_QUANT + e0 + 0] = xv.x + d.x;
    out[O_QUANT + e0 + 1] = xv.y + d.y;
    out[O_QUANT + e0 + 2] = xv.z + d.z;
    out[O_QUANT + e0 + 3] = xv.w + d.w;
    float s = d.x * d.x + d.y * d.y + d.z * d.z + d.w * d.w;
#pragma unroll
    for (int m = 16; m > 0; m >>= 1) s += __shfl_xor_sync(0xffffffffu, s, m);
    __shared__ float ws[8];
    int lane = threadIdx.x & 31, w = threadIdx.x >> 5;
    if (lane == 0) ws[w] = s;
    __syncthreads();
    if (w == 0) {
        float v = (lane < 8) ? ws[lane] : 0.0f;
#pragma unroll
        for (int m = 4; m > 0; m >>= 1) v += __shfl_xor_sync(0xffffffffu, v, m);
        if (lane == 0) atomicAdd(&g_loss_accum, v);
    }
}

// ---------------- kernel C: one-hot encodings ----------------------------------
#define ENC_ROWS 32
__global__ void enc_kernel(float* __restrict__ out) {
    int base = blockIdx.x * ENC_ROWS;
    int t = threadIdx.x;   // 256
    for (int r = 0; r < ENC_ROWS; r++) {
        int n = base + r;
        int idx = g_idx[n];
        float2* row = (float2*)(out + O_ENC + (size_t)n * N_E);
        int hot = idx >> 1;
        float2 hv = (idx & 1) ? make_float2(0.0f, 1.0f) : make_float2(1.0f, 0.0f);
#pragma unroll
        for (int rr = 0; rr < 2; rr++) {
            int slot = t + rr * 256;
            row[slot] = (slot == hot) ? hv : make_float2(0.0f, 0.0f);
        }
    }
}

// ---------------- kernel D: perplexity + loss finalize --------------------------
__global__ void final_kernel(float* __restrict__ out) {
    int t = threadIdx.x;   // 1024 threads
    float p = (float)g_counts[t] * (1.0f / 65536.0f);
    float s = p * logf(p + 1e-10f);
#pragma unroll
    for (int m = 16; m > 0; m >>= 1) s += __shfl_xor_sync(0xffffffffu, s, m);
    __shared__ float ws[32];
    int lane = t & 31, w = t >> 5;
    if (lane == 0) ws[w] = s;
    __syncthreads();
    if (w == 0) {
        float v = ws[lane];
#pragma unroll
        for (int m = 16; m > 0; m >>= 1) v += __shfl_xor_sync(0xffffffffu, v, m);
        if (lane == 0) {
            out[O_PERP] = expf(-v);
            out[O_LOSS] = 1.25f * g_loss_accum * (1.0f / (float)TOTAL);
        }
    }
}

// ---------------- launch ---------------------------------------------------------
extern "C" void kernel_launch(void* const* d_in, const int* in_sizes, int n_in,
                              void* d_out, int out_size) {
    const float* x  = (const float*)d_in[0];
    const float* ew = (const float*)d_in[1];
    if (n_in >= 2 && in_sizes[0] == N_E * DIM && in_sizes[1] == TOTAL) {
        x  = (const float*)d_in[1];
        ew = (const float*)d_in[0];
    }
    float* out = (float*)d_out;

    init_kernel<<<N_E / 128, 128>>>(ew);

    size_t smem = (size_t)2 * DIM * LDP * sizeof(float);   // 67,584 B
    cudaFuncSetAttribute(argmin_kernel,
                         cudaFuncAttributeMaxDynamicSharedMemorySize, (int)smem);
    argmin_kernel<<<N_Q / TQ, 256, smem>>>(x, ew);

    quant_loss_kernel<<<TOTAL / 4 / 256, 256>>>(x, ew, out);
    enc_kernel<<<N_Q / ENC_ROWS, 256>>>(out);
    final_kernel<<<1, 1024>>>(out);
}

// round 6
// speedup vs baseline: 1.8399x; 1.7473x over previous
#include <cuda_runtime.h>
#include <cuda_fp16.h>
#include <math.h>
#include <stdint.h>

// Problem constants
#define N_Q   65536
#define N_E   1024
#define DIM   64
#define HW    4096
#define TOTAL 4194304    // 16*64*4096

// Output layout: loss[1] | quantized[TOTAL] | perplexity[1] | encodings[N_Q*N_E]
#define O_QUANT 1UL
#define O_PERP  4194305UL
#define O_ENC   4194306UL

// ---------------- device scratch --------------------------------------------------
__device__ __align__(256) __half g_xh[N_Q * DIM];
__device__ __align__(256) __half g_xl[N_Q * DIM];
__device__ __align__(256) __half g_eh[N_E * DIM];
__device__ __align__(256) __half g_el[N_E * DIM];
__device__ int   g_idx[N_Q];
__device__ int   g_counts[N_E];
__device__ float g_loss_accum;
__device__ float g_enorm_half[N_E];

// ---------------- mma / ldmatrix helpers (base PTX ISA, no 'a' feature) -----------
__device__ __forceinline__ uint32_t smem_u32(const void* p) {
    uint32_t a;
    asm("{ .reg .u64 t; cvta.to.shared.u64 t, %1; cvt.u32.u64 %0, t; }" : "=r"(a) : "l"(p));
    return a;
}
__device__ __forceinline__ void ldsm_x4(uint32_t* r, uint32_t addr) {
    asm volatile("ldmatrix.sync.aligned.m8n8.x4.shared.b16 {%0,%1,%2,%3}, [%4];"
                 : "=r"(r[0]), "=r"(r[1]), "=r"(r[2]), "=r"(r[3]) : "r"(addr));
}
// B tile is [n][k] row-major in smem -> NON-transposed x2 gives the
// (k=(lane%4)*2+{0,1}, n=lane/4) fragment that mma row.col expects.
__device__ __forceinline__ void ldsm_x2(uint32_t* r, uint32_t addr) {
    asm volatile("ldmatrix.sync.aligned.m8n8.x2.shared.b16 {%0,%1}, [%2];"
                 : "=r"(r[0]), "=r"(r[1]) : "r"(addr));
}
__device__ __forceinline__ void mma16816(float* c, const uint32_t* a, const uint32_t* b) {
    asm volatile("mma.sync.aligned.m16n8k16.row.col.f32.f16.f16.f32 "
                 "{%0,%1,%2,%3}, {%4,%5,%6,%7}, {%8,%9}, {%0,%1,%2,%3};"
                 : "+f"(c[0]), "+f"(c[1]), "+f"(c[2]), "+f"(c[3])
                 : "r"(a[0]), "r"(a[1]), "r"(a[2]), "r"(a[3]), "r"(b[0]), "r"(b[1]));
}

// ---------------- prep: codebook split + norms + zero accum ------------------------
__global__ void prep_e_kernel(const float* __restrict__ ew) {
    int j = blockIdx.x * 128 + threadIdx.x;   // 1024 codes
    g_counts[j] = 0;
    if (j == 0) g_loss_accum = 0.0f;
    const float4* p = (const float4*)(ew + (size_t)j * DIM);
    float s = 0.0f;
#pragma unroll
    for (int i = 0; i < 16; i++) {
        float4 v = p[i];
        float c[4] = {v.x, v.y, v.z, v.w};
#pragma unroll
        for (int m = 0; m < 4; m++) {
            s += c[m] * c[m];
            __half h = __float2half_rn(c[m]);
            __half l = __float2half_rn(c[m] - __half2float(h));
            g_eh[(size_t)j * DIM + i * 4 + m] = h;
            g_el[(size_t)j * DIM + i * 4 + m] = l;
        }
    }
    g_enorm_half[j] = 0.5f * s;
}

// ---------------- prep: inputs NCHW -> per-query fp16 hi/lo rows --------------------
__global__ void prep_x_kernel(const float* __restrict__ x) {
    __shared__ float tile[64 * 65];
    int b  = blockIdx.x >> 6;
    int h0 = (blockIdx.x & 63) * 64;
    const float* xb = x + (size_t)b * (DIM * HW) + h0;
    int tid = threadIdx.x;   // 256
    for (int i = tid; i < 4096; i += 256) {
        int k = i >> 6, h = i & 63;
        tile[h * 65 + k] = xb[(size_t)k * HW + h];
    }
    __syncthreads();
    for (int i = tid; i < 4096; i += 256) {
        int h = i >> 6, k = i & 63;
        float v = tile[h * 65 + k];
        __half hi = __float2half_rn(v);
        __half lo = __float2half_rn(v - __half2float(hi));
        size_t n = (size_t)b * HW + h0 + h;
        g_xh[n * DIM + k] = hi;
        g_xl[n * DIM + k] = lo;
    }
}

// ---------------- kernel A: split-fp16 HMMA GEMM + argmin ---------------------------
// smem layout (bytes). half tiles are [128 rows][72 halves] (pad -> conflict-free ldmatrix)
#define LDH 72
#define SM_XH 0
#define SM_XL 18432
#define SM_EH 36864
#define SM_EL 55296
#define SM_EN 73728                    // 128 floats
#define SM_RV 74240                    // red_val: 128*4 floats
#define SM_RI 76288                    // red_idx: 128*4 ints
#define SM_SZ 78336

__global__ __launch_bounds__(256, 2) void argmin_mma_kernel() {
    extern __shared__ char smem[];
    uint32_t sb = smem_u32(smem);
    int tid  = threadIdx.x;
    int wid  = tid >> 5, lane = tid & 31;
    int wm   = wid & 1;        // m-block 0..1 (64 rows each)
    int wn   = wid >> 1;       // n-block 0..3 (32 cols each)
    int qbase = blockIdx.x * 128;

    float* ensm   = (float*)(smem + SM_EN);
    float* redv   = (float*)(smem + SM_RV);
    int*   redi   = (int*)  (smem + SM_RI);

    // Load X tiles (hi & lo): 128 rows x 8 segs of 16B
    for (int i = tid; i < 1024; i += 256) {
        int r = i >> 3, s = i & 7;
        uint32_t off = (uint32_t)(r * LDH + s * 8) * 2;
        *(uint4*)(smem + SM_XH + off) = *(const uint4*)&g_xh[(size_t)(qbase + r) * DIM + s * 8];
        *(uint4*)(smem + SM_XL + off) = *(const uint4*)&g_xl[(size_t)(qbase + r) * DIM + s * 8];
    }

    // per-thread ldmatrix address components
    int aRow = wm * 64 + (lane & 15);          // + mi*16 ; col k0 + (lane>>4)*8
    int aKof = (lane >> 4) * 8;
    int bRow = wn * 32 + (lane & 7);           // + ni*8  ; col k0 + ((lane>>3)&1)*8
    int bKof = ((lane >> 3) & 1) * 8;

    float bestV[8];
    int   bestI[8];
#pragma unroll
    for (int s = 0; s < 8; s++) { bestV[s] = 3.4e38f; bestI[s] = 0; }

    for (int chunk = 0; chunk < 8; chunk++) {
        int j0 = chunk * 128;
        __syncthreads();   // prior-chunk consumers done before overwrite
        if (tid < 128) ensm[tid] = g_enorm_half[j0 + tid];
        for (int i = tid; i < 1024; i += 256) {
            int r = i >> 3, s = i & 7;
            uint32_t off = (uint32_t)(r * LDH + s * 8) * 2;
            *(uint4*)(smem + SM_EH + off) = *(const uint4*)&g_eh[(size_t)(j0 + r) * DIM + s * 8];
            *(uint4*)(smem + SM_EL + off) = *(const uint4*)&g_el[(size_t)(j0 + r) * DIM + s * 8];
        }
        __syncthreads();

        float acc[4][4][4];
#pragma unroll
        for (int mi = 0; mi < 4; mi++)
#pragma unroll
            for (int ni = 0; ni < 4; ni++)
#pragma unroll
                for (int r = 0; r < 4; r++) acc[mi][ni][r] = 0.0f;

#pragma unroll
        for (int ks = 0; ks < 4; ks++) {
            int k0 = ks * 16;
            uint32_t ah[4][4], bh[4][2];
#pragma unroll
            for (int mi = 0; mi < 4; mi++)
                ldsm_x4(ah[mi], sb + SM_XH + (uint32_t)((aRow + mi * 16) * LDH + k0 + aKof) * 2);
#pragma unroll
            for (int ni = 0; ni < 4; ni++)
                ldsm_x2(bh[ni], sb + SM_EH + (uint32_t)((bRow + ni * 8) * LDH + k0 + bKof) * 2);
#pragma unroll
            for (int mi = 0; mi < 4; mi++)
#pragma unroll
                for (int ni = 0; ni < 4; ni++) mma16816(acc[mi][ni], ah[mi], bh[ni]);

            uint32_t bl[4][2];
#pragma unroll
            for (int ni = 0; ni < 4; ni++)
                ldsm_x2(bl[ni], sb + SM_EL + (uint32_t)((bRow + ni * 8) * LDH + k0 + bKof) * 2);
#pragma unroll
            for (int mi = 0; mi < 4; mi++)
#pragma unroll
                for (int ni = 0; ni < 4; ni++) mma16816(acc[mi][ni], ah[mi], bl[ni]);

            uint32_t al[4][4];
#pragma unroll
            for (int mi = 0; mi < 4; mi++)
                ldsm_x4(al[mi], sb + SM_XL + (uint32_t)((aRow + mi * 16) * LDH + k0 + aKof) * 2);
#pragma unroll
            for (int mi = 0; mi < 4; mi++)
#pragma unroll
                for (int ni = 0; ni < 4; ni++) mma16816(acc[mi][ni], al[mi], bh[ni]);
        }

        // epilogue: per-row argmin over this chunk's 128 codes
        float enr[8];
#pragma unroll
        for (int ni = 0; ni < 4; ni++) {
            int j = wn * 32 + ni * 8 + (lane & 3) * 2;
            enr[ni * 2]     = ensm[j];
            enr[ni * 2 + 1] = ensm[j + 1];
        }
        int g = lane >> 2;   // row-in-8 group
#pragma unroll
        for (int mi = 0; mi < 4; mi++) {
#pragma unroll
            for (int h = 0; h < 2; h++) {
                float v = 3.4e38f; int ix = 0;
#pragma unroll
                for (int ni = 0; ni < 4; ni++) {
#pragma unroll
                    for (int b = 0; b < 2; b++) {
                        float cand = enr[ni * 2 + b] - acc[mi][ni][h * 2 + b];
                        int col = j0 + wn * 32 + ni * 8 + (lane & 3) * 2 + b;
                        if (cand < v) { v = cand; ix = col; }
                    }
                }
#pragma unroll
                for (int m = 1; m < 4; m <<= 1) {
                    float ov = __shfl_xor_sync(0xffffffffu, v, m);
                    int   oi = __shfl_xor_sync(0xffffffffu, ix, m);
                    if (ov < v || (ov == v && oi < ix)) { v = ov; ix = oi; }
                }
                if ((lane & 3) == 0) {
                    int row = wm * 64 + mi * 16 + g + h * 8;
                    redv[row * 4 + wn] = v;
                    redi[row * 4 + wn] = ix;
                }
            }
        }
        __syncthreads();

        // owners (warps 0,1; lanes %4==0) fold the 4 n-slabs into running best
        if (wn == 0 && (lane & 3) == 0) {
            int slot = 0;
#pragma unroll
            for (int mi = 0; mi < 4; mi++) {
#pragma unroll
                for (int h = 0; h < 2; h++) {
                    int row = wm * 64 + mi * 16 + g + h * 8;
#pragma unroll
                    for (int w = 0; w < 4; w++) {
                        float ov = redv[row * 4 + w];
                        int   oi = redi[row * 4 + w];
                        if (ov < bestV[slot] || (ov == bestV[slot] && oi < bestI[slot])) {
                            bestV[slot] = ov; bestI[slot] = oi;
                        }
                    }
                    slot++;
                }
            }
        }
    }

    if (wn == 0 && (lane & 3) == 0) {
        int g = lane >> 2;
        int slot = 0;
#pragma unroll
        for (int mi = 0; mi < 4; mi++) {
#pragma unroll
            for (int h = 0; h < 2; h++) {
                int row = wm * 64 + mi * 16 + g + h * 8;
                g_idx[qbase + row] = bestI[slot];
                atomicAdd(&g_counts[bestI[slot]], 1);
                slot++;
            }
        }
    }
}

// ---------------- kernel B: gather + straight-through + loss ------------------------
__global__ void quant_loss_kernel(const float* __restrict__ x,
                                  const float* __restrict__ ew,
                                  float* __restrict__ out) {
    int t4 = blockIdx.x * 256 + threadIdx.x;
    int e0 = t4 * 4;
    int hw = e0 & (HW - 1);
    int c  = (e0 >> 12) & (DIM - 1);
    int b  = e0 >> 18;
    int n  = b * HW + hw;
    int4   idx4 = *(const int4*)&g_idx[n];
    float4 xv   = *(const float4*)&x[e0];
    float4 q;
    q.x = ew[(size_t)idx4.x * DIM + c];
    q.y = ew[(size_t)idx4.y * DIM + c];
    q.z = ew[(size_t)idx4.z * DIM + c];
    q.w = ew[(size_t)idx4.w * DIM + c];
    float4 d = make_float4(q.x - xv.x, q.y - xv.y, q.z - xv.z, q.w - xv.w);
    out[O_QUANT + e0 + 0] = xv.x + d.x;
    out[O_QUANT + e0 + 1] = xv.y + d.y;
    out[O_QUANT + e0 + 2] = xv.z + d.z;
    out[O_QUANT + e0 + 3] = xv.w + d.w;
    float s = d.x * d.x + d.y * d.y + d.z * d.z + d.w * d.w;
#pragma unroll
    for (int m = 16; m > 0; m >>= 1) s += __shfl_xor_sync(0xffffffffu, s, m);
    __shared__ float ws[8];
    int lane = threadIdx.x & 31, w = threadIdx.x >> 5;
    if (lane == 0) ws[w] = s;
    __syncthreads();
    if (w == 0) {
        float v = (lane < 8) ? ws[lane] : 0.0f;
#pragma unroll
        for (int m = 4; m > 0; m >>= 1) v += __shfl_xor_sync(0xffffffffu, v, m);
        if (lane == 0) atomicAdd(&g_loss_accum, v);
    }
}

// ---------------- kernel C: scatter ones into (memset-zeroed) encodings -------------
__global__ void enc_ones_kernel(float* __restrict__ out) {
    int n = blockIdx.x * 256 + threadIdx.x;
    out[O_ENC + (size_t)n * N_E + g_idx[n]] = 1.0f;
}

// ---------------- kernel D: perplexity + loss finalize -------------------------------
__global__ void final_kernel(float* __restrict__ out) {
    int t = threadIdx.x;   // 1024
    float p = (float)g_counts[t] * (1.0f / 65536.0f);
    float s = p * logf(p + 1e-10f);
#pragma unroll
    for (int m = 16; m > 0; m >>= 1) s += __shfl_xor_sync(0xffffffffu, s, m);
    __shared__ float ws[32];
    int lane = t & 31, w = t >> 5;
    if (lane == 0) ws[w] = s;
    __syncthreads();
    if (w == 0) {
        float v = ws[lane];
#pragma unroll
        for (int m = 16; m > 0; m >>= 1) v += __shfl_xor_sync(0xffffffffu, v, m);
        if (lane == 0) {
            out[O_PERP] = expf(-v);
            out[0] = 1.25f * g_loss_accum * (1.0f / (float)TOTAL);
        }
    }
}

// ---------------- launch ---------------------------------------------------------------
extern "C" void kernel_launch(void* const* d_in, const int* in_sizes, int n_in,
                              void* d_out, int out_size) {
    const float* x  = (const float*)d_in[0];
    const float* ew = (const float*)d_in[1];
    if (n_in >= 2 && in_sizes[0] == N_E * DIM && in_sizes[1] == TOTAL) {
        x  = (const float*)d_in[1];
        ew = (const float*)d_in[0];
    }
    float* out = (float*)d_out;

    prep_e_kernel<<<N_E / 128, 128>>>(ew);
    prep_x_kernel<<<1024, 256>>>(x);

    // zero the encodings region while argmin runs next on the same stream
    cudaMemsetAsync(out + O_ENC, 0, (size_t)N_Q * N_E * sizeof(float));

    cudaFuncSetAttribute(argmin_mma_kernel,
                         cudaFuncAttributeMaxDynamicSharedMemorySize, SM_SZ);
    argmin_mma_kernel<<<N_Q / 128, 256, SM_SZ>>>();

    quant_loss_kernel<<<TOTAL / 4 / 256, 256>>>(x, ew, out);
    enc_ones_kernel<<<N_Q / 256, 256>>>(out);
    final_kernel<<<1, 1024>>>(out);
}

// round 7
// speedup vs baseline: 2.1141x; 1.1490x over previous
#include <cuda_runtime.h>
#include <cuda_fp16.h>
#include <math.h>
#include <stdint.h>

// Problem constants
#define N_Q   65536
#define N_E   1024
#define DIM   64
#define HW    4096
#define TOTAL 4194304    // 16*64*4096

// Output layout: loss[1] | quantized[TOTAL] | perplexity[1] | encodings[N_Q*N_E]
#define O_QUANT 1UL
#define O_PERP  4194305UL
#define O_ENC   4194306UL

// ---------------- device scratch --------------------------------------------------
__device__ __align__(256) __half g_xh[N_Q * DIM];
__device__ __align__(256) __half g_xl[N_Q * DIM];
__device__ __align__(256) __half g_eh[N_E * DIM];
__device__ __align__(256) __half g_el[N_E * DIM];
__device__ __align__(256) float  g_ewT[DIM * N_E];   // transposed codebook [c][j]
__device__ int   g_idx[N_Q];
__device__ int   g_counts[N_E];
__device__ float g_loss_accum;
__device__ float g_enorm_half[N_E];

// ---------------- mma / ldmatrix helpers (base PTX ISA, no 'a' feature) -----------
__device__ __forceinline__ uint32_t smem_u32(const void* p) {
    uint32_t a;
    asm("{ .reg .u64 t; cvta.to.shared.u64 t, %1; cvt.u32.u64 %0, t; }" : "=r"(a) : "l"(p));
    return a;
}
__device__ __forceinline__ void ldsm_x4(uint32_t* r, uint32_t addr) {
    asm volatile("ldmatrix.sync.aligned.m8n8.x4.shared.b16 {%0,%1,%2,%3}, [%4];"
                 : "=r"(r[0]), "=r"(r[1]), "=r"(r[2]), "=r"(r[3]) : "r"(addr));
}
// B tile is [n][k] row-major in smem -> NON-transposed x2 gives the
// (k=(lane%4)*2+{0,1}, n=lane/4) fragment that mma row.col expects.
__device__ __forceinline__ void ldsm_x2(uint32_t* r, uint32_t addr) {
    asm volatile("ldmatrix.sync.aligned.m8n8.x2.shared.b16 {%0,%1}, [%2];"
                 : "=r"(r[0]), "=r"(r[1]) : "r"(addr));
}
__device__ __forceinline__ void mma16816(float* c, const uint32_t* a, const uint32_t* b) {
    asm volatile("mma.sync.aligned.m16n8k16.row.col.f32.f16.f16.f32 "
                 "{%0,%1,%2,%3}, {%4,%5,%6,%7}, {%8,%9}, {%0,%1,%2,%3};"
                 : "+f"(c[0]), "+f"(c[1]), "+f"(c[2]), "+f"(c[3])
                 : "r"(a[0]), "r"(a[1]), "r"(a[2]), "r"(a[3]), "r"(b[0]), "r"(b[1]));
}

// ---------------- prep: codebook split + norms + transpose + zero accum ------------
__global__ void prep_e_kernel(const float* __restrict__ ew) {
    __shared__ float ts[128 * 65];
    int tid = threadIdx.x;               // 128
    int j = blockIdx.x * 128 + tid;      // code index
    g_counts[j] = 0;
    if (j == 0) g_loss_accum = 0.0f;
    const float4* p = (const float4*)(ew + (size_t)j * DIM);
    float s = 0.0f;
#pragma unroll
    for (int i = 0; i < 16; i++) {
        float4 v = p[i];
        float c[4] = {v.x, v.y, v.z, v.w};
#pragma unroll
        for (int m = 0; m < 4; m++) {
            s += c[m] * c[m];
            __half h = __float2half_rn(c[m]);
            __half l = __float2half_rn(c[m] - __half2float(h));
            g_eh[(size_t)j * DIM + i * 4 + m] = h;
            g_el[(size_t)j * DIM + i * 4 + m] = l;
            ts[tid * 65 + i * 4 + m] = c[m];
        }
    }
    g_enorm_half[j] = 0.5f * s;
    __syncthreads();
    // coalesced transposed writes: g_ewT[c][j]
#pragma unroll 8
    for (int c = 0; c < 64; c++)
        g_ewT[(size_t)c * N_E + blockIdx.x * 128 + tid] = ts[tid * 65 + c];
}

// ---------------- prep: inputs NCHW -> per-query fp16 hi/lo rows --------------------
__global__ void prep_x_kernel(const float* __restrict__ x) {
    __shared__ float tile[64 * 65];
    int b  = blockIdx.x >> 6;
    int h0 = (blockIdx.x & 63) * 64;
    const float* xb = x + (size_t)b * (DIM * HW) + h0;
    int tid = threadIdx.x;   // 256
    for (int i = tid; i < 4096; i += 256) {
        int k = i >> 6, h = i & 63;
        tile[h * 65 + k] = xb[(size_t)k * HW + h];
    }
    __syncthreads();
    for (int i = tid; i < 4096; i += 256) {
        int h = i >> 6, k = i & 63;
        float v = tile[h * 65 + k];
        __half hi = __float2half_rn(v);
        __half lo = __float2half_rn(v - __half2float(hi));
        size_t n = (size_t)b * HW + h0 + h;
        g_xh[n * DIM + k] = hi;
        g_xl[n * DIM + k] = lo;
    }
}

// ---------------- kernel A: split-fp16 HMMA GEMM + argmin + one-hot writes ----------
// smem layout (bytes). half tiles are [128 rows][72 halves] (pad -> conflict-free ldmatrix)
#define LDH 72
#define SM_XH 0
#define SM_XL 18432
#define SM_EH 36864
#define SM_EL 55296
#define SM_EN 73728                    // 128 floats
#define SM_RV 74240                    // red_val: 128*4 floats
#define SM_RI 76288                    // red_idx: 128*4 ints
#define SM_IX 78336                    // final idx: 128 ints
#define SM_SZ 78848

__global__ __launch_bounds__(256, 2) void argmin_mma_kernel(float* __restrict__ out) {
    extern __shared__ char smem[];
    uint32_t sb = smem_u32(smem);
    int tid  = threadIdx.x;
    int wid  = tid >> 5, lane = tid & 31;
    int wm   = wid & 1;        // m-block 0..1 (64 rows each)
    int wn   = wid >> 1;       // n-block 0..3 (32 cols each)
    int qbase = blockIdx.x * 128;

    float* ensm   = (float*)(smem + SM_EN);
    float* redv   = (float*)(smem + SM_RV);
    int*   redi   = (int*)  (smem + SM_RI);
    int*   sm_ix  = (int*)  (smem + SM_IX);

    // Load X tiles (hi & lo): 128 rows x 8 segs of 16B
    for (int i = tid; i < 1024; i += 256) {
        int r = i >> 3, s = i & 7;
        uint32_t off = (uint32_t)(r * LDH + s * 8) * 2;
        *(uint4*)(smem + SM_XH + off) = *(const uint4*)&g_xh[(size_t)(qbase + r) * DIM + s * 8];
        *(uint4*)(smem + SM_XL + off) = *(const uint4*)&g_xl[(size_t)(qbase + r) * DIM + s * 8];
    }

    int aRow = wm * 64 + (lane & 15);
    int aKof = (lane >> 4) * 8;
    int bRow = wn * 32 + (lane & 7);
    int bKof = ((lane >> 3) & 1) * 8;

    float bestV[8];
    int   bestI[8];
#pragma unroll
    for (int s = 0; s < 8; s++) { bestV[s] = 3.4e38f; bestI[s] = 0; }

    for (int chunk = 0; chunk < 8; chunk++) {
        int j0 = chunk * 128;
        __syncthreads();
        if (tid < 128) ensm[tid] = g_enorm_half[j0 + tid];
        for (int i = tid; i < 1024; i += 256) {
            int r = i >> 3, s = i & 7;
            uint32_t off = (uint32_t)(r * LDH + s * 8) * 2;
            *(uint4*)(smem + SM_EH + off) = *(const uint4*)&g_eh[(size_t)(j0 + r) * DIM + s * 8];
            *(uint4*)(smem + SM_EL + off) = *(const uint4*)&g_el[(size_t)(j0 + r) * DIM + s * 8];
        }
        __syncthreads();

        float acc[4][4][4];
#pragma unroll
        for (int mi = 0; mi < 4; mi++)
#pragma unroll
            for (int ni = 0; ni < 4; ni++)
#pragma unroll
                for (int r = 0; r < 4; r++) acc[mi][ni][r] = 0.0f;

#pragma unroll
        for (int ks = 0; ks < 4; ks++) {
            int k0 = ks * 16;
            uint32_t ah[4][4], bh[4][2];
#pragma unroll
            for (int mi = 0; mi < 4; mi++)
                ldsm_x4(ah[mi], sb + SM_XH + (uint32_t)((aRow + mi * 16) * LDH + k0 + aKof) * 2);
#pragma unroll
            for (int ni = 0; ni < 4; ni++)
                ldsm_x2(bh[ni], sb + SM_EH + (uint32_t)((bRow + ni * 8) * LDH + k0 + bKof) * 2);
#pragma unroll
            for (int mi = 0; mi < 4; mi++)
#pragma unroll
                for (int ni = 0; ni < 4; ni++) mma16816(acc[mi][ni], ah[mi], bh[ni]);

            uint32_t bl[4][2];
#pragma unroll
            for (int ni = 0; ni < 4; ni++)
                ldsm_x2(bl[ni], sb + SM_EL + (uint32_t)((bRow + ni * 8) * LDH + k0 + bKof) * 2);
#pragma unroll
            for (int mi = 0; mi < 4; mi++)
#pragma unroll
                for (int ni = 0; ni < 4; ni++) mma16816(acc[mi][ni], ah[mi], bl[ni]);

            uint32_t al[4][4];
#pragma unroll
            for (int mi = 0; mi < 4; mi++)
                ldsm_x4(al[mi], sb + SM_XL + (uint32_t)((aRow + mi * 16) * LDH + k0 + aKof) * 2);
#pragma unroll
            for (int mi = 0; mi < 4; mi++)
#pragma unroll
                for (int ni = 0; ni < 4; ni++) mma16816(acc[mi][ni], al[mi], bh[ni]);
        }

        // epilogue: per-row argmin over this chunk's 128 codes
        float enr[8];
#pragma unroll
        for (int ni = 0; ni < 4; ni++) {
            int j = wn * 32 + ni * 8 + (lane & 3) * 2;
            enr[ni * 2]     = ensm[j];
            enr[ni * 2 + 1] = ensm[j + 1];
        }
        int g = lane >> 2;
#pragma unroll
        for (int mi = 0; mi < 4; mi++) {
#pragma unroll
            for (int h = 0; h < 2; h++) {
                float v = 3.4e38f; int ix = 0;
#pragma unroll
                for (int ni = 0; ni < 4; ni++) {
#pragma unroll
                    for (int b = 0; b < 2; b++) {
                        float cand = enr[ni * 2 + b] - acc[mi][ni][h * 2 + b];
                        int col = j0 + wn * 32 + ni * 8 + (lane & 3) * 2 + b;
                        if (cand < v) { v = cand; ix = col; }
                    }
                }
#pragma unroll
                for (int m = 1; m < 4; m <<= 1) {
                    float ov = __shfl_xor_sync(0xffffffffu, v, m);
                    int   oi = __shfl_xor_sync(0xffffffffu, ix, m);
                    if (ov < v || (ov == v && oi < ix)) { v = ov; ix = oi; }
                }
                if ((lane & 3) == 0) {
                    int row = wm * 64 + mi * 16 + g + h * 8;
                    redv[row * 4 + wn] = v;
                    redi[row * 4 + wn] = ix;
                }
            }
        }
        __syncthreads();

        if (wn == 0 && (lane & 3) == 0) {
            int slot = 0;
#pragma unroll
            for (int mi = 0; mi < 4; mi++) {
#pragma unroll
                for (int h = 0; h < 2; h++) {
                    int row = wm * 64 + mi * 16 + g + h * 8;
#pragma unroll
                    for (int w = 0; w < 4; w++) {
                        float ov = redv[row * 4 + w];
                        int   oi = redi[row * 4 + w];
                        if (ov < bestV[slot] || (ov == bestV[slot] && oi < bestI[slot])) {
                            bestV[slot] = ov; bestI[slot] = oi;
                        }
                    }
                    slot++;
                }
            }
        }
    }

    if (wn == 0 && (lane & 3) == 0) {
        int g = lane >> 2;
        int slot = 0;
#pragma unroll
        for (int mi = 0; mi < 4; mi++) {
#pragma unroll
            for (int h = 0; h < 2; h++) {
                int row = wm * 64 + mi * 16 + g + h * 8;
                g_idx[qbase + row] = bestI[slot];
                sm_ix[row] = bestI[slot];
                atomicAdd(&g_counts[bestI[slot]], 1);
                slot++;
            }
        }
    }
    __syncthreads();

    // one-hot encodings for this CTA's 128 rows (streaming stores, overlap with
    // other CTAs' tensor work). enc row base is 8B-aligned -> float2.
    float* encbase = out + O_ENC + (size_t)qbase * N_E;
    for (int r = 0; r < 128; r++) {
        int idx = sm_ix[r];
        float2* row = (float2*)(encbase + (size_t)r * N_E);
        int hot = idx >> 1;
        float2 hv = (idx & 1) ? make_float2(0.0f, 1.0f) : make_float2(1.0f, 0.0f);
#pragma unroll
        for (int rr = 0; rr < 2; rr++) {
            int slot = tid + rr * 256;
            float2 v = (slot == hot) ? hv : make_float2(0.0f, 0.0f);
            __stcs(&row[slot], v);
        }
    }
}

// ---------------- kernel B: gather (smem codebook column) + ST + loss ---------------
__global__ void quant_loss_kernel(const float* __restrict__ x,
                                  float* __restrict__ out) {
    __shared__ float col[1024];
    __shared__ float ws[8];
    int tid  = threadIdx.x;                 // 256
    int base = blockIdx.x * 1024;           // block covers 1024 elems, fixed (b,c)
    int c = (base >> 12) & (DIM - 1);
    int b = base >> 18;
    ((float4*)col)[tid] = ((const float4*)&g_ewT[(size_t)c * N_E])[tid];
    __syncthreads();

    int e0 = base + tid * 4;
    int hw = e0 & (HW - 1);
    int n  = b * HW + hw;
    int4   idx4 = *(const int4*)&g_idx[n];
    float4 xv   = *(const float4*)&x[e0];
    float4 q = make_float4(col[idx4.x], col[idx4.y], col[idx4.z], col[idx4.w]);
    float4 d = make_float4(q.x - xv.x, q.y - xv.y, q.z - xv.z, q.w - xv.w);
    out[O_QUANT + e0 + 0] = xv.x + d.x;
    out[O_QUANT + e0 + 1] = xv.y + d.y;
    out[O_QUANT + e0 + 2] = xv.z + d.z;
    out[O_QUANT + e0 + 3] = xv.w + d.w;
    float s = d.x * d.x + d.y * d.y + d.z * d.z + d.w * d.w;
#pragma unroll
    for (int m = 16; m > 0; m >>= 1) s += __shfl_xor_sync(0xffffffffu, s, m);
    int lane = tid & 31, w = tid >> 5;
    if (lane == 0) ws[w] = s;
    __syncthreads();
    if (w == 0) {
        float v = (lane < 8) ? ws[lane] : 0.0f;
#pragma unroll
        for (int m = 4; m > 0; m >>= 1) v += __shfl_xor_sync(0xffffffffu, v, m);
        if (lane == 0) atomicAdd(&g_loss_accum, v);
    }
}

// ---------------- kernel D: perplexity + loss finalize -------------------------------
__global__ void final_kernel(float* __restrict__ out) {
    int t = threadIdx.x;   // 1024
    float p = (float)g_counts[t] * (1.0f / 65536.0f);
    float s = p * logf(p + 1e-10f);
#pragma unroll
    for (int m = 16; m > 0; m >>= 1) s += __shfl_xor_sync(0xffffffffu, s, m);
    __shared__ float ws[32];
    int lane = t & 31, w = t >> 5;
    if (lane == 0) ws[w] = s;
    __syncthreads();
    if (w == 0) {
        float v = ws[lane];
#pragma unroll
        for (int m = 16; m > 0; m >>= 1) v += __shfl_xor_sync(0xffffffffu, v, m);
        if (lane == 0) {
            out[O_PERP] = expf(-v);
            out[0] = 1.25f * g_loss_accum * (1.0f / (float)TOTAL);
        }
    }
}

// ---------------- launch ---------------------------------------------------------------
extern "C" void kernel_launch(void* const* d_in, const int* in_sizes, int n_in,
                              void* d_out, int out_size) {
    const float* x  = (const float*)d_in[0];
    const float* ew = (const float*)d_in[1];
    if (n_in >= 2 && in_sizes[0] == N_E * DIM && in_sizes[1] == TOTAL) {
        x  = (const float*)d_in[1];
        ew = (const float*)d_in[0];
    }
    float* out = (float*)d_out;

    prep_e_kernel<<<N_E / 128, 128>>>(ew);
    prep_x_kernel<<<1024, 256>>>(x);

    cudaFuncSetAttribute(argmin_mma_kernel,
                         cudaFuncAttributeMaxDynamicSharedMemorySize, SM_SZ);
    argmin_mma_kernel<<<N_Q / 128, 256, SM_SZ>>>(out);

    quant_loss_kernel<<<TOTAL / 1024, 256>>>(x, out);
    final_kernel<<<1, 1024>>>(out);
}

// round 8
// speedup vs baseline: 2.1489x; 1.0165x over previous
#include <cuda_runtime.h>
#include <cuda_fp16.h>
#include <math.h>
#include <stdint.h>

// Problem constants
#define N_Q   65536
#define N_E   1024
#define DIM   64
#define HW    4096
#define TOTAL 4194304    // 16*64*4096

// Output layout: loss[1] | quantized[TOTAL] | perplexity[1] | encodings[N_Q*N_E]
#define O_QUANT 1UL
#define O_PERP  4194305UL
#define O_ENC   4194306UL

// ---------------- device scratch --------------------------------------------------
__device__ __align__(256) __half g_eh[N_E * DIM];
__device__ __align__(256) __half g_el[N_E * DIM];
__device__ int   g_counts[N_E];
__device__ float g_loss_accum;
__device__ float g_enorm_half[N_E];

// ---------------- mma / ldmatrix helpers (base PTX ISA, no 'a' feature) -----------
__device__ __forceinline__ uint32_t smem_u32(const void* p) {
    uint32_t a;
    asm("{ .reg .u64 t; cvta.to.shared.u64 t, %1; cvt.u32.u64 %0, t; }" : "=r"(a) : "l"(p));
    return a;
}
__device__ __forceinline__ void ldsm_x4(uint32_t* r, uint32_t addr) {
    asm volatile("ldmatrix.sync.aligned.m8n8.x4.shared.b16 {%0,%1,%2,%3}, [%4];"
                 : "=r"(r[0]), "=r"(r[1]), "=r"(r[2]), "=r"(r[3]) : "r"(addr));
}
// B tile is [n][k] row-major in smem -> NON-transposed x2 gives the
// (k=(lane%4)*2+{0,1}, n=lane/4) fragment that mma row.col expects.
__device__ __forceinline__ void ldsm_x2(uint32_t* r, uint32_t addr) {
    asm volatile("ldmatrix.sync.aligned.m8n8.x2.shared.b16 {%0,%1}, [%2];"
                 : "=r"(r[0]), "=r"(r[1]) : "r"(addr));
}
__device__ __forceinline__ void mma16816(float* c, const uint32_t* a, const uint32_t* b) {
    asm volatile("mma.sync.aligned.m16n8k16.row.col.f32.f16.f16.f32 "
                 "{%0,%1,%2,%3}, {%4,%5,%6,%7}, {%8,%9}, {%0,%1,%2,%3};"
                 : "+f"(c[0]), "+f"(c[1]), "+f"(c[2]), "+f"(c[3])
                 : "r"(a[0]), "r"(a[1]), "r"(a[2]), "r"(a[3]), "r"(b[0]), "r"(b[1]));
}

// ---------------- prep: codebook split + norms + zero accum ------------------------
__global__ void prep_e_kernel(const float* __restrict__ ew) {
    int tid = threadIdx.x;               // 128
    int j = blockIdx.x * 128 + tid;      // code index
    g_counts[j] = 0;
    if (j == 0) g_loss_accum = 0.0f;
    const float4* p = (const float4*)(ew + (size_t)j * DIM);
    float s = 0.0f;
#pragma unroll
    for (int i = 0; i < 16; i++) {
        float4 v = p[i];
        float c[4] = {v.x, v.y, v.z, v.w};
#pragma unroll
        for (int m = 0; m < 4; m++) {
            s += c[m] * c[m];
            __half h = __float2half_rn(c[m]);
            __half l = __float2half_rn(c[m] - __half2float(h));
            g_eh[(size_t)j * DIM + i * 4 + m] = h;
            g_el[(size_t)j * DIM + i * 4 + m] = l;
        }
    }
    g_enorm_half[j] = 0.5f * s;
}

// ---------------- kernel A: fully fused VQ -----------------------------------------
// smem layout (bytes). half tiles [128 rows][LDH=72 halves]
#define LDH 72
#define LDQ 129
#define SM_XH 0
#define SM_XL 18432
#define SM_EH 36864
#define SM_EL 55296
#define SM_EN 73728                    // 128 floats
#define SM_RV 74240                    // red_val: 128*4 floats
#define SM_RI 76288                    // red_idx: 128*4 ints
#define SM_IX 78336                    // final idx: 128 ints
#define SM_SZ 78848
// quant tile reuses bytes [0 .. 64*LDQ*4) = 33024 after MMA is done

__global__ __launch_bounds__(256, 2) void argmin_mma_kernel(const float* __restrict__ x,
                                                            const float* __restrict__ ew,
                                                            float* __restrict__ out) {
    extern __shared__ char smem[];
    uint32_t sb = smem_u32(smem);
    int tid  = threadIdx.x;
    int wid  = tid >> 5, lane = tid & 31;
    int wm   = wid & 1;        // m-block 0..1 (64 rows each)
    int wn   = wid >> 1;       // n-block 0..3 (32 cols each)
    int qbase = blockIdx.x * 128;
    int b   = qbase >> 12;          // batch
    int hw0 = qbase & (HW - 1);     // hw offset (tile never crosses batch)

    float* ensm   = (float*)(smem + SM_EN);
    float* redv   = (float*)(smem + SM_RV);
    int*   redi   = (int*)  (smem + SM_RI);
    int*   sm_ix  = (int*)  (smem + SM_IX);
    __half* Xs  = (__half*)(smem + SM_XH);
    __half* XLs = (__half*)(smem + SM_XL);

    // ---- fused prep_x: load 128 queries from NCHW, split to hi/lo fp16 in smem ----
    const float* xg = x + (size_t)b * (DIM * HW) + hw0;
#pragma unroll 4
    for (int i = 0; i < 32; i++) {
        int linear = i * 256 + tid;
        int k = linear >> 7, h = linear & 127;
        float v = xg[(size_t)k * HW + h];         // coalesced
        __half hi = __float2half_rn(v);
        __half lo = __float2half_rn(v - __half2float(hi));
        Xs [h * LDH + k] = hi;
        XLs[h * LDH + k] = lo;
    }

    int aRow = wm * 64 + (lane & 15);
    int aKof = (lane >> 4) * 8;
    int bRow = wn * 32 + (lane & 7);
    int bKof = ((lane >> 3) & 1) * 8;

    float bestV[8];
    int   bestI[8];
#pragma unroll
    for (int s = 0; s < 8; s++) { bestV[s] = 3.4e38f; bestI[s] = 0; }

    for (int chunk = 0; chunk < 8; chunk++) {
        int j0 = chunk * 128;
        __syncthreads();
        if (tid < 128) ensm[tid] = g_enorm_half[j0 + tid];
        for (int i = tid; i < 1024; i += 256) {
            int r = i >> 3, s = i & 7;
            uint32_t off = (uint32_t)(r * LDH + s * 8) * 2;
            *(uint4*)(smem + SM_EH + off) = *(const uint4*)&g_eh[(size_t)(j0 + r) * DIM + s * 8];
            *(uint4*)(smem + SM_EL + off) = *(const uint4*)&g_el[(size_t)(j0 + r) * DIM + s * 8];
        }
        __syncthreads();

        float acc[4][4][4];
#pragma unroll
        for (int mi = 0; mi < 4; mi++)
#pragma unroll
            for (int ni = 0; ni < 4; ni++)
#pragma unroll
                for (int r = 0; r < 4; r++) acc[mi][ni][r] = 0.0f;

#pragma unroll
        for (int ks = 0; ks < 4; ks++) {
            int k0 = ks * 16;
            uint32_t ah[4][4], bh[4][2];
#pragma unroll
            for (int mi = 0; mi < 4; mi++)
                ldsm_x4(ah[mi], sb + SM_XH + (uint32_t)((aRow + mi * 16) * LDH + k0 + aKof) * 2);
#pragma unroll
            for (int ni = 0; ni < 4; ni++)
                ldsm_x2(bh[ni], sb + SM_EH + (uint32_t)((bRow + ni * 8) * LDH + k0 + bKof) * 2);
#pragma unroll
            for (int mi = 0; mi < 4; mi++)
#pragma unroll
                for (int ni = 0; ni < 4; ni++) mma16816(acc[mi][ni], ah[mi], bh[ni]);

            uint32_t bl[4][2];
#pragma unroll
            for (int ni = 0; ni < 4; ni++)
                ldsm_x2(bl[ni], sb + SM_EL + (uint32_t)((bRow + ni * 8) * LDH + k0 + bKof) * 2);
#pragma unroll
            for (int mi = 0; mi < 4; mi++)
#pragma unroll
                for (int ni = 0; ni < 4; ni++) mma16816(acc[mi][ni], ah[mi], bl[ni]);

            uint32_t al[4][4];
#pragma unroll
            for (int mi = 0; mi < 4; mi++)
                ldsm_x4(al[mi], sb + SM_XL + (uint32_t)((aRow + mi * 16) * LDH + k0 + aKof) * 2);
#pragma unroll
            for (int mi = 0; mi < 4; mi++)
#pragma unroll
                for (int ni = 0; ni < 4; ni++) mma16816(acc[mi][ni], al[mi], bh[ni]);
        }

        // epilogue: per-row argmin over this chunk's 128 codes
        float enr[8];
#pragma unroll
        for (int ni = 0; ni < 4; ni++) {
            int j = wn * 32 + ni * 8 + (lane & 3) * 2;
            enr[ni * 2]     = ensm[j];
            enr[ni * 2 + 1] = ensm[j + 1];
        }
        int g = lane >> 2;
#pragma unroll
        for (int mi = 0; mi < 4; mi++) {
#pragma unroll
            for (int h = 0; h < 2; h++) {
                float v = 3.4e38f; int ix = 0;
#pragma unroll
                for (int ni = 0; ni < 4; ni++) {
#pragma unroll
                    for (int bb = 0; bb < 2; bb++) {
                        float cand = enr[ni * 2 + bb] - acc[mi][ni][h * 2 + bb];
                        int col = j0 + wn * 32 + ni * 8 + (lane & 3) * 2 + bb;
                        if (cand < v) { v = cand; ix = col; }
                    }
                }
#pragma unroll
                for (int m = 1; m < 4; m <<= 1) {
                    float ov = __shfl_xor_sync(0xffffffffu, v, m);
                    int   oi = __shfl_xor_sync(0xffffffffu, ix, m);
                    if (ov < v || (ov == v && oi < ix)) { v = ov; ix = oi; }
                }
                if ((lane & 3) == 0) {
                    int row = wm * 64 + mi * 16 + g + h * 8;
                    redv[row * 4 + wn] = v;
                    redi[row * 4 + wn] = ix;
                }
            }
        }
        __syncthreads();

        if (wn == 0 && (lane & 3) == 0) {
            int slot = 0;
#pragma unroll
            for (int mi = 0; mi < 4; mi++) {
#pragma unroll
                for (int h = 0; h < 2; h++) {
                    int row = wm * 64 + mi * 16 + g + h * 8;
#pragma unroll
                    for (int w = 0; w < 4; w++) {
                        float ov = redv[row * 4 + w];
                        int   oi = redi[row * 4 + w];
                        if (ov < bestV[slot] || (ov == bestV[slot] && oi < bestI[slot])) {
                            bestV[slot] = ov; bestI[slot] = oi;
                        }
                    }
                    slot++;
                }
            }
        }
    }

    if (wn == 0 && (lane & 3) == 0) {
        int g = lane >> 2;
        int slot = 0;
#pragma unroll
        for (int mi = 0; mi < 4; mi++) {
#pragma unroll
            for (int h = 0; h < 2; h++) {
                int row = wm * 64 + mi * 16 + g + h * 8;
                sm_ix[row] = bestI[slot];
                atomicAdd(&g_counts[bestI[slot]], 1);
                slot++;
            }
        }
    }
    __syncthreads();

    // ---- one-hot encodings: 1 float4 store per thread per row (streaming) ----------
    float* encbase = out + O_ENC + (size_t)qbase * N_E;
    for (int r = 0; r < 128; r++) {
        int idx = sm_ix[r];
        float* row = encbase + (size_t)r * N_E;
        if (tid < 255) {
            int c0 = 2 + 4 * tid;
            float4 v = make_float4(0.0f, 0.0f, 0.0f, 0.0f);
            if ((unsigned)(idx - c0) < 4u) ((float*)&v)[idx - c0] = 1.0f;
            __stcs((float4*)(row + c0), v);
        } else {
            float2 hd = make_float2(idx == 0 ? 1.0f : 0.0f, idx == 1 ? 1.0f : 0.0f);
            __stcs((float2*)row, hd);
            float2 tl = make_float2(idx == 1022 ? 1.0f : 0.0f, idx == 1023 ? 1.0f : 0.0f);
            __stcs((float2*)(row + 1022), tl);
        }
    }

    // ---- fused quantize + straight-through + loss -----------------------------------
    // Phase 1: gather ew rows into smem tile qt[k][h] (reuses the X tile region).
    float* qt = (float*)smem;   // [64][LDQ]
    {
        int h = tid & 127, half = tid >> 7;
        int idx = sm_ix[h];
        const float4* er = (const float4*)(ew + (size_t)idx * DIM + half * 32);
#pragma unroll
        for (int i = 0; i < 8; i++) {
            float4 v = er[i];
            int k = half * 32 + i * 4;
            qt[(k + 0) * LDQ + h] = v.x;
            qt[(k + 1) * LDQ + h] = v.y;
            qt[(k + 2) * LDQ + h] = v.z;
            qt[(k + 3) * LDQ + h] = v.w;
        }
    }
    __syncthreads();

    // Phase 2: coalesced x re-read + quantized write + loss partial.
    float* qout = out + O_QUANT + (size_t)b * (DIM * HW) + hw0;
    float lsum = 0.0f;
#pragma unroll 4
    for (int i = 0; i < 32; i++) {
        int linear = i * 256 + tid;
        int k = linear >> 7, h = linear & 127;
        float xv = xg[(size_t)k * HW + h];
        float q  = qt[k * LDQ + h];
        float d  = q - xv;
        qout[(size_t)k * HW + h] = xv + d;   // straight-through forward value
        lsum += d * d;
    }
#pragma unroll
    for (int m = 16; m > 0; m >>= 1) lsum += __shfl_xor_sync(0xffffffffu, lsum, m);
    if (lane == 0) redv[wid] = lsum;   // redv region is free now
    __syncthreads();
    if (wid == 0) {
        float v = (lane < 8) ? redv[lane] : 0.0f;
#pragma unroll
        for (int m = 4; m > 0; m >>= 1) v += __shfl_xor_sync(0xffffffffu, v, m);
        if (lane == 0) atomicAdd(&g_loss_accum, v);
    }
}

// ---------------- kernel D: perplexity + loss finalize -------------------------------
__global__ void final_kernel(float* __restrict__ out) {
    int t = threadIdx.x;   // 1024
    float p = (float)g_counts[t] * (1.0f / 65536.0f);
    float s = p * logf(p + 1e-10f);
#pragma unroll
    for (int m = 16; m > 0; m >>= 1) s += __shfl_xor_sync(0xffffffffu, s, m);
    __shared__ float ws[32];
    int lane = t & 31, w = t >> 5;
    if (lane == 0) ws[w] = s;
    __syncthreads();
    if (w == 0) {
        float v = ws[lane];
#pragma unroll
        for (int m = 16; m > 0; m >>= 1) v += __shfl_xor_sync(0xffffffffu, v, m);
        if (lane == 0) {
            out[O_PERP] = expf(-v);
            out[0] = 1.25f * g_loss_accum * (1.0f / (float)TOTAL);
        }
    }
}

// ---------------- launch ---------------------------------------------------------------
extern "C" void kernel_launch(void* const* d_in, const int* in_sizes, int n_in,
                              void* d_out, int out_size) {
    const float* x  = (const float*)d_in[0];
    const float* ew = (const float*)d_in[1];
    if (n_in >= 2 && in_sizes[0] == N_E * DIM && in_sizes[1] == TOTAL) {
        x  = (const float*)d_in[1];
        ew = (const float*)d_in[0];
    }
    float* out = (float*)d_out;

    prep_e_kernel<<<N_E / 128, 128>>>(ew);

    cudaFuncSetAttribute(argmin_mma_kernel,
                         cudaFuncAttributeMaxDynamicSharedMemorySize, SM_SZ);
    argmin_mma_kernel<<<N_Q / 128, 256, SM_SZ>>>(x, ew, out);

    final_kernel<<<1, 1024>>>(out);
}